// round 1
// baseline (speedup 1.0000x reference)
#include <cuda_runtime.h>
#include <cstdint>

// ---------------------------------------------------------------------------
// HDCTokenEncoder: out[b,i,d] = item_memory[tok[b,i]][(d - i) mod D] * (1/sqrt(D))
// item_memory entries are exactly +/-1  =>  row L2 norm == sqrt(D) == 100 exactly.
// So normalization is a constant scale 0.01f. Pure bandwidth problem.
//
// Strategy: bucket (b,i) positions by token (V=256 buckets), then one block per
// (token, split) loads the 40KB row into SMEM once and emits several rotated,
// scaled output rows with aligned float4 loads/stores.
// ---------------------------------------------------------------------------

#define HDC_D      10000
#define HDC_D4     2500          // D / 4
#define HDC_S      2048          // sequence length (fixed for this problem)
#define MAX_BS     16384         // B * S
#define MAX_V      256
#define PSPLIT     8             // position-split factor per token

// Scratch (device globals: allocation-free per harness rules)
__device__ int g_counts[MAX_V];
__device__ int g_offsets[MAX_V + 1];
__device__ int g_cursors[MAX_V];
__device__ int g_positions[MAX_BS];

// ---- bucketing kernels -----------------------------------------------------

__global__ void k_init_counts(int V) {
    int t = blockIdx.x * blockDim.x + threadIdx.x;
    if (t < V) g_counts[t] = 0;
}

__global__ void k_count(const int* __restrict__ tok, int BS) {
    int i = blockIdx.x * blockDim.x + threadIdx.x;
    if (i < BS) atomicAdd(&g_counts[tok[i]], 1);
}

__global__ void k_scan(int V) {
    // single thread: V=256, trivial cost
    if (threadIdx.x == 0 && blockIdx.x == 0) {
        int acc = 0;
        g_offsets[0] = 0;
        for (int v = 0; v < V; ++v) {
            g_cursors[v] = acc;
            acc += g_counts[v];
            g_offsets[v + 1] = acc;
        }
    }
}

__global__ void k_scatter(const int* __restrict__ tok, int BS) {
    int i = blockIdx.x * blockDim.x + threadIdx.x;
    if (i < BS) {
        int t = tok[i];
        int pos = atomicAdd(&g_cursors[t], 1);
        g_positions[pos] = i;
    }
}

// ---- main encode kernel ------------------------------------------------------
// grid = (V, PSPLIT), block = 256 threads.
// Each block: load row[token] into SMEM (aligned float4), then for each assigned
// position bs (with roll r = bs % S) write the rotated, scaled row.
// Since D % 4 == 0, output group g (floats [4g,4g+3]) reads source floats
// [s0, s0+3] with s0 = (4g - r) mod D, spanning aligned float4s qa=s0>>2 and
// qa+1 (wrapping at D4). The intra-vec offset ofs = s0 & 3 = (-r) mod 4 is
// uniform across the block -> uniform branch, conflict-free LDS.128.

__global__ __launch_bounds__(256) void k_encode(const float* __restrict__ im,
                                                float* __restrict__ out,
                                                int S) {
    __shared__ float4 srow[HDC_D4];

    int t   = blockIdx.x;
    int beg = g_offsets[t];
    int end = g_offsets[t + 1];
    if (beg == end) return;

    // stage the token's row once (aligned, coalesced)
    const float4* src = reinterpret_cast<const float4*>(im + (size_t)t * HDC_D);
    for (int g = threadIdx.x; g < HDC_D4; g += blockDim.x)
        srow[g] = src[g];
    __syncthreads();

    const float scale = 0.01f;   // 1/sqrt(D), exact since rows are +/-1

    for (int p = beg + blockIdx.y; p < end; p += gridDim.y) {
        int bs = g_positions[p];
        int r  = bs % S;                         // roll amount = sequence position
        int ofs = (4 - (r & 3)) & 3;             // uniform intra-float4 offset
        float4* dst = reinterpret_cast<float4*>(out + (size_t)bs * HDC_D);

        for (int g = threadIdx.x; g < HDC_D4; g += blockDim.x) {
            int s0 = 4 * g - r;
            if (s0 < 0) s0 += HDC_D;             // r < S <= D, so one fixup suffices
            int qa = s0 >> 2;
            float4 A = srow[qa];
            float4 v;
            if (ofs == 0) {
                v = A;
            } else {
                int qb = qa + 1;
                if (qb == HDC_D4) qb = 0;        // wrap aligns with float4 boundary
                float4 Bv = srow[qb];
                if (ofs == 1)      v = make_float4(A.y, A.z, A.w, Bv.x);
                else if (ofs == 2) v = make_float4(A.z, A.w, Bv.x, Bv.y);
                else               v = make_float4(A.w, Bv.x, Bv.y, Bv.z);
            }
            v.x *= scale; v.y *= scale; v.z *= scale; v.w *= scale;
            __stcs(dst + g, v);                  // streaming store: don't pollute L2
        }
    }
}

// ---- launch ------------------------------------------------------------------

extern "C" void kernel_launch(void* const* d_in, const int* in_sizes, int n_in,
                              void* d_out, int out_size) {
    const int*   tok = (const int*)d_in[0];     // (B, S) int32
    const float* im  = (const float*)d_in[1];   // (V, D) float32
    float*       out = (float*)d_out;           // (B, S, D) float32

    int BS = in_sizes[0];                        // B*S = 16384
    int V  = in_sizes[1] / HDC_D;                // 256
    int S  = HDC_S;                              // 2048 (fixed shape)

    k_init_counts<<<(V + 255) / 256, 256>>>(V);
    k_count<<<(BS + 255) / 256, 256>>>(tok, BS);
    k_scan<<<1, 1>>>(V);
    k_scatter<<<(BS + 255) / 256, 256>>>(tok, BS);

    dim3 grid(V, PSPLIT);
    k_encode<<<grid, 256>>>(im, out, S);
}

// round 2
// speedup vs baseline: 1.2149x; 1.2149x over previous
#include <cuda_runtime.h>
#include <cstdint>

// ---------------------------------------------------------------------------
// HDCTokenEncoder: out[b,i,d] = item_memory[tok[b,i]][(d - i) mod D] * (1/sqrt(D))
// item_memory entries are exactly +/-1  =>  row L2 norm == sqrt(D) == 100 exactly,
// so normalization is a constant scale 0.01f (pre-applied while staging SMEM).
//
// Single-kernel design: block (t, y) scans the strided candidate positions
// { i : i % PSPLIT == y } for tok[i] == t (64KB token array is L2-resident,
// scan is ~1024 L2-hit LDGs per block), stages the token's 40KB row into SMEM
// once (pre-scaled), then writes each matching rotated output row with aligned
// float4 loads + streaming STG.128.
// ---------------------------------------------------------------------------

#define HDC_D      10000
#define HDC_D4     2500            // D / 4
#define HDC_S      2048            // sequence length (fixed shape, power of two)
#define HDC_BS     16384           // B * S
#define HDC_V      256
#define PSPLIT     16              // position-split factor per token
#define CAND       (HDC_BS / PSPLIT)   // 1024 candidates per block

__global__ __launch_bounds__(256) void k_encode(const int* __restrict__ tok,
                                                const float* __restrict__ im,
                                                float* __restrict__ out) {
    __shared__ float4 srow[HDC_D4];        // 40 KB: pre-scaled token row
    __shared__ int    list[CAND];          // 4 KB: matching (b*S+i) positions
    __shared__ int    nmatch;

    const int t = blockIdx.x;              // token id
    const int y = blockIdx.y;              // split index

    if (threadIdx.x == 0) nmatch = 0;
    __syncthreads();

    // Phase 1: find my positions. Candidate i = y + PSPLIT*j.
    #pragma unroll
    for (int j = threadIdx.x; j < CAND; j += 256) {
        int i = y + PSPLIT * j;
        if (__ldg(&tok[i]) == t) {
            int k = atomicAdd(&nmatch, 1);
            list[k] = i;
        }
    }
    __syncthreads();

    const int n = nmatch;
    if (n == 0) return;                    // ~1.8% of blocks; skip the row load

    // Phase 2: stage the row into SMEM, pre-scaled by 1/sqrt(D) = 0.01 exactly.
    const float scale = 0.01f;
    const float4* src = reinterpret_cast<const float4*>(im + (size_t)t * HDC_D);
    for (int g = threadIdx.x; g < HDC_D4; g += 256) {
        float4 v = src[g];
        v.x *= scale; v.y *= scale; v.z *= scale; v.w *= scale;
        srow[g] = v;
    }
    __syncthreads();

    // Phase 3: emit each rotated output row.
    // out float group g (floats 4g..4g+3) reads source floats starting at
    // s0 = (4g - r) mod D; since D%4==0 this spans two aligned float4s with a
    // block-uniform intra-vector offset ofs = (-r) mod 4.
    for (int p = 0; p < n; ++p) {
        const int bs  = list[p];
        const int r   = bs & (HDC_S - 1);          // roll = sequence position
        const int ofs = (4 - (r & 3)) & 3;         // uniform across block
        float4* dst = reinterpret_cast<float4*>(out + (size_t)bs * HDC_D);

        if (ofs == 0) {
            // r % 4 == 0: pure float4 copy with rotation by whole quads
            const int q0 = r >> 2;                 // rotate-right by q0 quads
            for (int g = threadIdx.x; g < HDC_D4; g += 256) {
                int qa = g - q0;
                if (qa < 0) qa += HDC_D4;
                __stcs(dst + g, srow[qa]);
            }
        } else {
            for (int g = threadIdx.x; g < HDC_D4; g += 256) {
                int s0 = 4 * g - r;
                if (s0 < 0) s0 += HDC_D;           // r < S <= D: one fixup suffices
                int qa = s0 >> 2;
                int qb = qa + 1;
                if (qb == HDC_D4) qb = 0;          // wrap lands on float4 boundary
                float4 A = srow[qa];
                float4 Bv = srow[qb];
                float4 v;
                if (ofs == 1)      v = make_float4(A.y, A.z, A.w, Bv.x);
                else if (ofs == 2) v = make_float4(A.z, A.w, Bv.x, Bv.y);
                else               v = make_float4(A.w, Bv.x, Bv.y, Bv.z);
                __stcs(dst + g, v);
            }
        }
    }
}

extern "C" void kernel_launch(void* const* d_in, const int* in_sizes, int n_in,
                              void* d_out, int out_size) {
    const int*   tok = (const int*)d_in[0];     // (B, S) int32
    const float* im  = (const float*)d_in[1];   // (V, D) float32
    float*       out = (float*)d_out;           // (B, S, D) float32
    (void)in_sizes; (void)n_in; (void)out_size;

    dim3 grid(HDC_V, PSPLIT);
    k_encode<<<grid, 256>>>(tok, im, out);
}

// round 3
// speedup vs baseline: 1.2467x; 1.0262x over previous
#include <cuda_runtime.h>
#include <cstdint>

// ---------------------------------------------------------------------------
// HDCTokenEncoder: out[b,i,d] = item_memory[tok[b,i]][(d - i) mod D] * (1/sqrt(D))
// item_memory entries are exactly +/-1 => row L2 norm == sqrt(D) == 100 exactly,
// so normalization is the constant scale 0.01f (pre-applied while staging SMEM).
//
// Block (t, y) scans strided candidate positions { i : i % PSPLIT == y } for
// tok[i] == t (token array is L2-resident), stages the token's 40KB row into
// SMEM once (pre-scaled), then writes each matching rotated output row using
// aligned LDS.128 + streaming STG.128. 512 threads/block -> 4 CTAs/SM (warp
// limit) with 176KB smem, doubling in-flight stores vs the 256-thread variant.
// ---------------------------------------------------------------------------

#define HDC_D      10000
#define HDC_D4     2500            // D / 4
#define HDC_S      2048            // sequence length (fixed, power of two)
#define HDC_BS     16384           // B * S
#define HDC_V      256
#define PSPLIT     16              // position-split factor per token
#define CAND       (HDC_BS / PSPLIT)   // 1024 candidates per block
#define NTHR       512

// Blend A (lower quad) with B (next quad) at intra-quad offset OFS (1..3).
template <int OFS>
__device__ __forceinline__ float4 blend(float4 A, float4 B) {
    if (OFS == 1) return make_float4(A.y, A.z, A.w, B.x);
    if (OFS == 2) return make_float4(A.z, A.w, B.x, B.y);
    return make_float4(A.w, B.x, B.y, B.z);
}

template <int OFS>
__device__ __forceinline__ void emit_row(const float4* __restrict__ srow,
                                         float4* __restrict__ dst, int r) {
    // first source quad index for output quad g = threadIdx.x
    int s0 = 4 * (int)threadIdx.x - r;
    if (s0 < 0) s0 += HDC_D;
    int qa = s0 >> 2;
    for (int g = threadIdx.x; g < HDC_D4; g += NTHR) {
        float4 v;
        if (OFS == 0) {
            v = srow[qa];
        } else {
            int qb = qa + 1;
            if (qb == HDC_D4) qb = 0;      // wrap lands on a quad boundary
            v = blend<OFS>(srow[qa], srow[qb]);
        }
        __stcs(dst + g, v);
        qa += NTHR;
        if (qa >= HDC_D4) qa -= HDC_D4;
    }
}

__global__ __launch_bounds__(NTHR) void k_encode(const int* __restrict__ tok,
                                                 const float* __restrict__ im,
                                                 float* __restrict__ out) {
    __shared__ float4 srow[HDC_D4];        // 40 KB: pre-scaled token row
    __shared__ int    list[CAND];          // 4 KB: matching (b*S+i) positions
    __shared__ int    nmatch;

    const int t = blockIdx.x;              // token id
    const int y = blockIdx.y;              // split index

    if (threadIdx.x == 0) nmatch = 0;
    __syncthreads();

    // Phase 1: find my positions (candidate i = y + PSPLIT*j), L2-hit loads.
    #pragma unroll
    for (int j = threadIdx.x; j < CAND; j += NTHR) {
        int i = y + PSPLIT * j;
        if (__ldg(&tok[i]) == t) {
            int k = atomicAdd(&nmatch, 1);
            list[k] = i;
        }
    }
    __syncthreads();

    const int n = nmatch;
    if (n == 0) return;                    // skip the row load entirely

    // Phase 2: stage the row, pre-scaled by 1/sqrt(D) = 0.01 exactly.
    const float scale = 0.01f;
    const float4* src = reinterpret_cast<const float4*>(im + (size_t)t * HDC_D);
    for (int g = threadIdx.x; g < HDC_D4; g += NTHR) {
        float4 v = src[g];
        v.x *= scale; v.y *= scale; v.z *= scale; v.w *= scale;
        srow[g] = v;
    }
    __syncthreads();

    // Phase 3: emit rotated rows. Rotation r = sequence position; intra-quad
    // offset ofs = (-r) mod 4 is uniform across the block.
    for (int p = 0; p < n; ++p) {
        const int bs  = list[p];
        const int r   = bs & (HDC_S - 1);
        float4* dst = reinterpret_cast<float4*>(out + (size_t)bs * HDC_D);
        switch ((4 - (r & 3)) & 3) {
            case 0: emit_row<0>(srow, dst, r); break;
            case 1: emit_row<1>(srow, dst, r); break;
            case 2: emit_row<2>(srow, dst, r); break;
            default: emit_row<3>(srow, dst, r); break;
        }
    }
}

extern "C" void kernel_launch(void* const* d_in, const int* in_sizes, int n_in,
                              void* d_out, int out_size) {
    const int*   tok = (const int*)d_in[0];     // (B, S) int32
    const float* im  = (const float*)d_in[1];   // (V, D) float32
    float*       out = (float*)d_out;           // (B, S, D) float32
    (void)in_sizes; (void)n_in; (void)out_size;

    dim3 grid(HDC_V, PSPLIT);
    k_encode<<<grid, NTHR>>>(tok, im, out);
}